// round 10
// baseline (speedup 1.0000x reference)
#include <cuda_runtime.h>
#include <cuda_bf16.h>
#include <math.h>
#include <stdint.h>

#define BATCH 4
#define CH    256
#define HWN   4096
#define GROUPS 32
#define CPG   8
#define NHEADS 4
#define HD    64
#define EPSV  1e-5f
#define QSCALE 0.18033688011112042f   // 0.125 * log2(e)

// ---- scratch (__device__ globals; allocation-free) ----
__device__ __nv_bfloat16 g_xnb [BATCH*HWN*CH];  // GN(x), [b][n][c]
__device__ __nv_bfloat16 g_kvnb[BATCH*HWN*CH];  // GN(cond), [b][n][c]
__device__ __nv_bfloat16 g_qb[BATCH*CH*HWN];    // [b][h][n][d], pre-scaled
__device__ __nv_bfloat16 g_kb[BATCH*CH*HWN];    // [b][h][n][d]
__device__ __nv_bfloat16 g_vb[BATCH*CH*HWN];    // [b][c][n]
__device__ __nv_bfloat16 g_aob[BATCH*HWN*CH];   // attn out, [b][n][c]
__device__ __nv_bfloat16 g_wqb[CH*CH], g_wkb[CH*CH], g_wvb[CH*CH], g_wob[CH*CH];

__device__ __forceinline__ float fast_exp2(float x) {
    float y; asm("ex2.approx.f32 %0, %1;" : "=f"(y) : "f"(x)); return y;
}
__device__ __forceinline__ uint32_t pack_bf16x2(float lo, float hi) {
    uint32_t r;
    asm("cvt.rn.satfinite.bf16x2.f32 %0, %1, %2;" : "=r"(r) : "f"(hi), "f"(lo));
    return r;
}
__device__ __forceinline__ void mma_bf16(float* d, const uint32_t* a,
                                         uint32_t b0, uint32_t b1) {
    asm volatile(
        "mma.sync.aligned.m16n8k16.row.col.f32.bf16.bf16.f32 "
        "{%0,%1,%2,%3}, {%4,%5,%6,%7}, {%8,%9}, {%0,%1,%2,%3};\n"
        : "+f"(d[0]), "+f"(d[1]), "+f"(d[2]), "+f"(d[3])
        : "r"(a[0]), "r"(a[1]), "r"(a[2]), "r"(a[3]), "r"(b0), "r"(b1));
}
__device__ __forceinline__ void ldsm_x4(uint32_t& r0, uint32_t& r1,
                                        uint32_t& r2, uint32_t& r3, uint32_t sa) {
    asm volatile("ldmatrix.sync.aligned.m8n8.x4.shared.b16 {%0,%1,%2,%3}, [%4];"
                 : "=r"(r0), "=r"(r1), "=r"(r2), "=r"(r3) : "r"(sa));
}
__device__ __forceinline__ uint32_t smem_u32(const void* p) {
    return (uint32_t)__cvta_generic_to_shared(p);
}
__device__ __forceinline__ void cp16(uint32_t dst, const void* src) {
    asm volatile("cp.async.cg.shared.global [%0], [%1], 16;" :: "r"(dst), "l"(src));
}
#define CP_COMMIT() asm volatile("cp.async.commit_group;" ::: "memory")
#define CP_WAIT0()  asm volatile("cp.async.wait_group 0;" ::: "memory")

// =====================================================================
// Weight fp32 -> bf16
// =====================================================================
__global__ void wconv_kernel(const float* __restrict__ wq,
                             const float* __restrict__ wk,
                             const float* __restrict__ wv,
                             const float* __restrict__ wo)
{
    const int i = blockIdx.x * 256 + threadIdx.x;
    g_wqb[i] = __float2bfloat16_rn(wq[i]);
    g_wkb[i] = __float2bfloat16_rn(wk[i]);
    g_wvb[i] = __float2bfloat16_rn(wv[i]);
    g_wob[i] = __float2bfloat16_rn(wo[i]);
}

// =====================================================================
// GroupNorm -> bf16 [b][n][c]
// =====================================================================
__global__ void gn_kernel(const float* __restrict__ x,
                          const float* __restrict__ cond,
                          const float* __restrict__ gqw, const float* __restrict__ gqb,
                          const float* __restrict__ gkw, const float* __restrict__ gkb)
{
    const int kv = blockIdx.y;
    const float* in  = kv ? cond : x;
    __nv_bfloat16* outb = kv ? g_kvnb : g_xnb;
    const float* gw  = kv ? gkw : gqw;
    const float* gb  = kv ? gkb : gqb;

    const int b = blockIdx.x / GROUPS;
    const int g = blockIdx.x % GROUPS;
    const size_t base_off = ((size_t)b*CH + (size_t)g*CPG) * HWN;
    const float4* in4 = (const float4*)(in + base_off);

    float s = 0.f, ss = 0.f;
    for (int i = threadIdx.x; i < (CPG*HWN)/4; i += 256) {
        float4 v = in4[i];
        s  += v.x + v.y + v.z + v.w;
        ss += v.x*v.x + v.y*v.y + v.z*v.z + v.w*v.w;
    }
    #pragma unroll
    for (int off = 16; off; off >>= 1) {
        s  += __shfl_xor_sync(0xffffffffu, s,  off);
        ss += __shfl_xor_sync(0xffffffffu, ss, off);
    }
    __shared__ float sm_s[8], sm_ss[8];
    if ((threadIdx.x & 31) == 0) { sm_s[threadIdx.x>>5] = s; sm_ss[threadIdx.x>>5] = ss; }
    __syncthreads();
    s = 0.f; ss = 0.f;
    #pragma unroll
    for (int w = 0; w < 8; w++) { s += sm_s[w]; ss += sm_ss[w]; }

    const float inv_n = 1.f / (float)(CPG*HWN);
    const float mean  = s * inv_n;
    const float var   = ss * inv_n - mean*mean;
    const float rstd  = rsqrtf(var + EPSV);

    float gwv[CPG], gbv[CPG];
    #pragma unroll
    for (int c = 0; c < CPG; c++) {
        gwv[c] = gw[g*CPG + c] * rstd;
        gbv[c] = gb[g*CPG + c] - mean * gwv[c];
    }

    const float* inp = in + base_off;
    for (int px = threadIdx.x; px < HWN; px += 256) {
        uint32_t p[4];
        #pragma unroll
        for (int c2 = 0; c2 < 4; c2++) {
            float v0 = inp[(size_t)(2*c2  )*HWN + px] * gwv[2*c2  ] + gbv[2*c2  ];
            float v1 = inp[(size_t)(2*c2+1)*HWN + px] * gwv[2*c2+1] + gbv[2*c2+1];
            p[c2] = pack_bf16x2(v0, v1);
        }
        *(uint4*)&outb[((size_t)b*HWN + px)*CH + g*CPG] =
            make_uint4(p[0], p[1], p[2], p[3]);
    }
}

// =====================================================================
// bf16 mma GEMM core, double-buffered SMEM (1 sync per k-chunk).
// Block 128ch x 128px; 8 warps 64x32.
// mode: 0=fp32 [b][c][n]+bias+res  1=q bf16 [b][h][n][d]*QSCALE
//       2=k bf16 [b][h][n][d]      3=v bf16 [b][c][n]
// =====================================================================
#define WT_STR 72
#define CS_STR 136
#define GEMM_SMEM 73728

__device__ __forceinline__ void gemm_core(
    char* buf,
    const __nv_bfloat16* __restrict__ Wb,
    const __nv_bfloat16* __restrict__ Xb,
    const float* __restrict__ bias,
    __nv_bfloat16* __restrict__ outb,
    int mode,
    const float* __restrict__ res,
    float* __restrict__ outf,
    int b, int m0, int n0)
{
    __nv_bfloat16* Wt[2] = { (__nv_bfloat16*)buf,
                             (__nv_bfloat16*)buf + 18432 };
    __nv_bfloat16* Xt[2] = { (__nv_bfloat16*)buf + 9216,
                             (__nv_bfloat16*)buf + 27648 };
    __nv_bfloat16* Cs = (__nv_bfloat16*)buf;   // epilogue restage (q/k)

    const int t = threadIdx.x;
    const int lane = t & 31, warp = t >> 5;
    const int g = lane >> 2, qt = lane & 3;
    const int wm = warp >> 2, wn = warp & 3;
    const int srow = t >> 3, sseg = (t & 7) * 8;

    float acc[4][4][4];
    #pragma unroll
    for (int i = 0; i < 4; i++)
        #pragma unroll
        for (int j = 0; j < 4; j++)
            #pragma unroll
            for (int l = 0; l < 4; l++) acc[i][j][l] = 0.f;

    uint4 wreg[4], xreg[4];
    #pragma unroll
    for (int it = 0; it < 4; it++) {
        int row = srow + it*32;
        wreg[it] = *(const uint4*)&Wb[(size_t)(m0+row)*CH + sseg];
        xreg[it] = *(const uint4*)&Xb[((size_t)b*HWN + n0+row)*CH + sseg];
    }
    #pragma unroll
    for (int it = 0; it < 4; it++) {
        int row = srow + it*32;
        *(uint4*)&Wt[0][row*WT_STR + sseg] = wreg[it];
        *(uint4*)&Xt[0][row*WT_STR + sseg] = xreg[it];
    }
    __syncthreads();

    for (int c = 0; c < 4; c++) {
        const int cur = c & 1;
        if (c + 1 < 4) {
            const int k0 = (c+1)*64;
            #pragma unroll
            for (int it = 0; it < 4; it++) {
                int row = srow + it*32;
                wreg[it] = *(const uint4*)&Wb[(size_t)(m0+row)*CH + k0 + sseg];
                xreg[it] = *(const uint4*)&Xb[((size_t)b*HWN + n0+row)*CH + k0 + sseg];
            }
        }
        const __nv_bfloat16* Wc = Wt[cur];
        const __nv_bfloat16* Xc = Xt[cur];
        #pragma unroll
        for (int kc = 0; kc < 4; kc++) {
            uint32_t a[4][4], b0[4], b1[4];
            #pragma unroll
            for (int mf = 0; mf < 4; mf++) {
                const __nv_bfloat16* wr = Wc + (wm*64 + mf*16 + g)*WT_STR + kc*16 + 2*qt;
                a[mf][0] = *(const uint32_t*)wr;
                a[mf][1] = *(const uint32_t*)(wr + 8*WT_STR);
                a[mf][2] = *(const uint32_t*)(wr + 8);
                a[mf][3] = *(const uint32_t*)(wr + 8*WT_STR + 8);
            }
            #pragma unroll
            for (int nf = 0; nf < 4; nf++) {
                const __nv_bfloat16* xr = Xc + (wn*32 + nf*8 + g)*WT_STR + kc*16 + 2*qt;
                b0[nf] = *(const uint32_t*)xr;
                b1[nf] = *(const uint32_t*)(xr + 8);
            }
            #pragma unroll
            for (int mf = 0; mf < 4; mf++)
                #pragma unroll
                for (int nf = 0; nf < 4; nf++)
                    mma_bf16(acc[mf][nf], a[mf], b0[nf], b1[nf]);
        }
        if (c + 1 < 4) {
            #pragma unroll
            for (int it = 0; it < 4; it++) {
                int row = srow + it*32;
                *(uint4*)&Wt[1-cur][row*WT_STR + sseg] = wreg[it];
                *(uint4*)&Xt[1-cur][row*WT_STR + sseg] = xreg[it];
            }
            __syncthreads();
        }
    }

    if (mode == 0) {
        #pragma unroll
        for (int mf = 0; mf < 4; mf++) {
            const int ch = m0 + wm*64 + mf*16 + g;
            const float bb0 = bias[ch], bb1 = bias[ch + 8];
            #pragma unroll
            for (int nf = 0; nf < 4; nf++) {
                const int px = n0 + wn*32 + nf*8 + 2*qt;
                const size_t o0 = ((size_t)b*CH + ch)*HWN + px;
                const size_t o1 = ((size_t)b*CH + ch + 8)*HWN + px;
                float2 r0 = *(const float2*)&res[o0];
                float2 r1 = *(const float2*)&res[o1];
                *(float2*)&outf[o0] = make_float2(acc[mf][nf][0] + bb0 + r0.x,
                                                  acc[mf][nf][1] + bb0 + r0.y);
                *(float2*)&outf[o1] = make_float2(acc[mf][nf][2] + bb1 + r1.x,
                                                  acc[mf][nf][3] + bb1 + r1.y);
            }
        }
    } else if (mode == 3) {
        #pragma unroll
        for (int mf = 0; mf < 4; mf++) {
            const int ch = m0 + wm*64 + mf*16 + g;
            const float bb0 = bias[ch], bb1 = bias[ch + 8];
            #pragma unroll
            for (int nf = 0; nf < 4; nf++) {
                const int px = n0 + wn*32 + nf*8 + 2*qt;
                *(uint32_t*)&outb[((size_t)b*CH + ch)*HWN + px] =
                    pack_bf16x2(acc[mf][nf][0] + bb0, acc[mf][nf][1] + bb0);
                *(uint32_t*)&outb[((size_t)b*CH + ch + 8)*HWN + px] =
                    pack_bf16x2(acc[mf][nf][2] + bb1, acc[mf][nf][3] + bb1);
            }
        }
    } else {
        const float sc = (mode == 1) ? QSCALE : 1.0f;
        __syncthreads();
        #pragma unroll
        for (int mf = 0; mf < 4; mf++) {
            const int chl = wm*64 + mf*16 + g;
            const float bb0 = bias[m0 + chl], bb1 = bias[m0 + chl + 8];
            #pragma unroll
            for (int nf = 0; nf < 4; nf++) {
                const int pxl = wn*32 + nf*8 + 2*qt;
                Cs[pxl*CS_STR + chl]       = __float2bfloat16_rn((acc[mf][nf][0] + bb0) * sc);
                Cs[(pxl+1)*CS_STR + chl]   = __float2bfloat16_rn((acc[mf][nf][1] + bb0) * sc);
                Cs[pxl*CS_STR + chl+8]     = __float2bfloat16_rn((acc[mf][nf][2] + bb1) * sc);
                Cs[(pxl+1)*CS_STR + chl+8] = __float2bfloat16_rn((acc[mf][nf][3] + bb1) * sc);
            }
        }
        __syncthreads();
        #pragma unroll
        for (int it = 0; it < 8; it++) {
            int i = t + it*256;
            int px = i >> 4, seg = i & 15;
            uint4 v = *(const uint4*)&Cs[px*CS_STR + seg*8];
            const int h = (m0 >> 6) + (seg >> 3);
            const int d = (seg & 7) * 8;
            *(uint4*)&outb[((size_t)(b*NHEADS + h)*HWN + n0 + px)*HD + d] = v;
        }
    }
}

// fused q/k/v launch: grid (32, 2, 12); z = mat*4 + b
__global__ void __launch_bounds__(256, 2) gemm_qkv_kernel(
    const float* __restrict__ bq, const float* __restrict__ bk,
    const float* __restrict__ bv)
{
    extern __shared__ char dbuf[];
    const int z = blockIdx.z;
    const int mat = z >> 2, b = z & 3;
    const __nv_bfloat16* W = (mat == 0) ? g_wqb : (mat == 1) ? g_wkb : g_wvb;
    const float* bias      = (mat == 0) ? bq   : (mat == 1) ? bk   : bv;
    __nv_bfloat16* out     = (mat == 0) ? g_qb : (mat == 1) ? g_kb : g_vb;
    const __nv_bfloat16* X = (mat == 0) ? g_xnb : g_kvnb;
    gemm_core(dbuf, W, X, bias, out, mat + 1, nullptr, nullptr,
              b, blockIdx.y * 128, blockIdx.x * 128);
}

// wo projection: grid (32, 2, 4)
__global__ void __launch_bounds__(256, 2) gemm_wo_kernel(
    const float* __restrict__ bo, const float* __restrict__ res,
    float* __restrict__ outf)
{
    extern __shared__ char dbuf[];
    gemm_core(dbuf, g_wob, g_aob, bo, nullptr, 0, res, outf,
              blockIdx.z, blockIdx.y * 128, blockIdx.x * 128);
}

// =====================================================================
// bf16 mma flash attention; cp.async double-buffered K/V (1 sync/tile,
// copies fully overlapped with compute).
// =====================================================================
#define KS_STR 72
#define KVBUF (64*KS_STR)            // elems per K (or V) buffer

__global__ void __launch_bounds__(256, 2) attn_mma_bf16()
{
    __shared__ __nv_bfloat16 kvsm[4*KVBUF];  // K0,V0 | K1,V1

    const int bh = blockIdx.y;
    const int b = bh >> 2, h = bh & 3;
    const int n0 = blockIdx.x * 128;
    const __nv_bfloat16* Qg = g_qb + (size_t)(b*NHEADS + h) * HWN * HD;
    const __nv_bfloat16* Kg = g_kb + (size_t)(b*NHEADS + h) * HWN * HD;
    const __nv_bfloat16* Vg = g_vb + ((size_t)b*CH + (size_t)h*HD) * HWN;

    const int t = threadIdx.x;
    const int lane = t & 31, warp = t >> 5;
    const int g = lane >> 2, tid = lane & 3;
    const int nb = warp * 16;

    const uint32_t lds_off = (uint32_t)(((lane & 7) * KS_STR + (lane >> 3) * 8) * 2);
    const uint32_t kv_base = smem_u32(kvsm) + lds_off;

    const int srow0 = t >> 3,        sseg = (t & 7) * 8;
    const int srow1 = srow0 + 32;
    const uint32_t cp_base = smem_u32(kvsm);
    const uint32_t dK0 = cp_base + (uint32_t)((srow0*KS_STR + sseg) * 2);
    const uint32_t dK1 = cp_base + (uint32_t)((srow1*KS_STR + sseg) * 2);
    const uint32_t dV0 = dK0 + KVBUF*2;
    const uint32_t dV1 = dK1 + KVBUF*2;

    uint32_t qa[4][4];
    {
        const __nv_bfloat16* q0 = Qg + (size_t)(n0 + nb + g) * HD;
        const __nv_bfloat16* q1 = Qg + (size_t)(n0 + nb + g + 8) * HD;
        #pragma unroll
        for (int kc = 0; kc < 4; kc++) {
            qa[kc][0] = *(const uint32_t*)(q0 + kc*16 + 2*tid);
            qa[kc][1] = *(const uint32_t*)(q1 + kc*16 + 2*tid);
            qa[kc][2] = *(const uint32_t*)(q0 + kc*16 + 2*tid + 8);
            qa[kc][3] = *(const uint32_t*)(q1 + kc*16 + 2*tid + 8);
        }
    }

    float oa[8][4];
    #pragma unroll
    for (int i = 0; i < 8; i++)
        #pragma unroll
        for (int j = 0; j < 4; j++) oa[i][j] = 0.f;
    float ls0 = 0.f, ls1 = 0.f;

    // prologue: async-copy tile 0 into buffer 0
    cp16(dK0, Kg + (size_t)srow0*HD + sseg);
    cp16(dK1, Kg + (size_t)srow1*HD + sseg);
    cp16(dV0, Vg + (size_t)srow0*HWN + sseg);
    cp16(dV1, Vg + (size_t)srow1*HWN + sseg);
    CP_COMMIT();
    CP_WAIT0();
    __syncthreads();

    for (int tile = 0; tile < HWN/64; tile++) {
        const int cur = tile & 1;
        const uint32_t bufb = (uint32_t)(cur * 2*KVBUF * 2);   // bytes
        const bool more = (tile + 1 < HWN/64);

        // issue async copy of next tile into the idle buffer
        if (more) {
            const int j1 = (tile + 1) * 64;
            const uint32_t ob = (uint32_t)((1-cur) * 2*KVBUF * 2);
            cp16(dK0 + ob, Kg + (size_t)(j1+srow0)*HD + sseg);
            cp16(dK1 + ob, Kg + (size_t)(j1+srow1)*HD + sseg);
            cp16(dV0 + ob, Vg + (size_t)srow0*HWN + j1 + sseg);
            cp16(dV1 + ob, Vg + (size_t)srow1*HWN + j1 + sseg);
            CP_COMMIT();
        }

        // ---- S = Q K^T ----
        float sa[8][4];
        #pragma unroll
        for (int mt = 0; mt < 8; mt++) {
            uint32_t kb[8];
            const uint32_t base = kv_base + bufb + (uint32_t)(mt * 8 * KS_STR * 2);
            ldsm_x4(kb[0], kb[1], kb[2], kb[3], base);
            ldsm_x4(kb[4], kb[5], kb[6], kb[7], base + 64);
            #pragma unroll
            for (int j = 0; j < 4; j++) sa[mt][j] = 0.f;
            #pragma unroll
            for (int kc = 0; kc < 4; kc++)
                mma_bf16(sa[mt], qa[kc], kb[2*kc], kb[2*kc+1]);
        }

        // ---- exp2 + pack P in registers ----
        uint32_t pe[4][4];
        #pragma unroll
        for (int kc = 0; kc < 4; kc++) {
            float e00 = fast_exp2(sa[2*kc][0]);
            float e01 = fast_exp2(sa[2*kc][1]);
            float e02 = fast_exp2(sa[2*kc][2]);
            float e03 = fast_exp2(sa[2*kc][3]);
            float e10 = fast_exp2(sa[2*kc+1][0]);
            float e11 = fast_exp2(sa[2*kc+1][1]);
            float e12 = fast_exp2(sa[2*kc+1][2]);
            float e13 = fast_exp2(sa[2*kc+1][3]);
            ls0 += e00 + e01 + e10 + e11;
            ls1 += e02 + e03 + e12 + e13;
            pe[kc][0] = pack_bf16x2(e00, e01);
            pe[kc][1] = pack_bf16x2(e02, e03);
            pe[kc][2] = pack_bf16x2(e10, e11);
            pe[kc][3] = pack_bf16x2(e12, e13);
        }

        // ---- O += P V^T ----
        const uint32_t vbase = kv_base + bufb + (uint32_t)(KVBUF * 2);
        #pragma unroll
        for (int dt = 0; dt < 8; dt++) {
            uint32_t vb[8];
            const uint32_t base = vbase + (uint32_t)(dt * 8 * KS_STR * 2);
            ldsm_x4(vb[0], vb[1], vb[2], vb[3], base);
            ldsm_x4(vb[4], vb[5], vb[6], vb[7], base + 64);
            #pragma unroll
            for (int kc = 0; kc < 4; kc++)
                mma_bf16(oa[dt], pe[kc], vb[2*kc], vb[2*kc+1]);
        }

        if (more) {
            CP_WAIT0();
            __syncthreads();
        }
    }

    // ---- normalize + store bf16 [b][n][c] ----
    ls0 += __shfl_xor_sync(0xffffffffu, ls0, 1);
    ls0 += __shfl_xor_sync(0xffffffffu, ls0, 2);
    ls1 += __shfl_xor_sync(0xffffffffu, ls1, 1);
    ls1 += __shfl_xor_sync(0xffffffffu, ls1, 2);
    const float li0 = 1.f / ls0;
    const float li1 = 1.f / ls1;

    __nv_bfloat16* O0 = g_aob + ((size_t)b*HWN + n0 + nb + g)*CH + h*HD + 2*tid;
    __nv_bfloat16* O1 = O0 + 8*CH;
    #pragma unroll
    for (int dt = 0; dt < 8; dt++) {
        *(uint32_t*)(O0 + dt*8) = pack_bf16x2(oa[dt][0]*li0, oa[dt][1]*li0);
        *(uint32_t*)(O1 + dt*8) = pack_bf16x2(oa[dt][2]*li1, oa[dt][3]*li1);
    }
}

// =====================================================================
extern "C" void kernel_launch(void* const* d_in, const int* in_sizes, int n_in,
                              void* d_out, int out_size)
{
    const float* x    = (const float*)d_in[0];
    const float* cond = (const float*)d_in[1];
    const float* gqw  = (const float*)d_in[2];
    const float* gqb  = (const float*)d_in[3];
    const float* gkw  = (const float*)d_in[4];
    const float* gkb  = (const float*)d_in[5];
    const float* wq   = (const float*)d_in[6];
    const float* bq   = (const float*)d_in[7];
    const float* wk   = (const float*)d_in[8];
    const float* bk   = (const float*)d_in[9];
    const float* wv   = (const float*)d_in[10];
    const float* bv   = (const float*)d_in[11];
    const float* wo   = (const float*)d_in[12];
    const float* bo   = (const float*)d_in[13];
    float* out = (float*)d_out;

    cudaFuncSetAttribute(gemm_qkv_kernel,
                         cudaFuncAttributeMaxDynamicSharedMemorySize, GEMM_SMEM);
    cudaFuncSetAttribute(gemm_wo_kernel,
                         cudaFuncAttributeMaxDynamicSharedMemorySize, GEMM_SMEM);

    wconv_kernel<<<CH*CH/256, 256>>>(wq, wk, wv, wo);
    gn_kernel<<<dim3(BATCH*GROUPS, 2), 256>>>(x, cond, gqw, gqb, gkw, gkb);

    gemm_qkv_kernel<<<dim3(HWN/128, CH/128, 12), 256, GEMM_SMEM>>>(bq, bk, bv);

    attn_mma_bf16<<<dim3(HWN/128, BATCH*NHEADS), 256>>>();

    gemm_wo_kernel<<<dim3(HWN/128, CH/128, BATCH), 256, GEMM_SMEM>>>(bo, x, out);
}

// round 11
// speedup vs baseline: 1.1539x; 1.1539x over previous
#include <cuda_runtime.h>
#include <cuda_fp16.h>
#include <math.h>
#include <stdint.h>

#define BATCH 4
#define CH    256
#define HWN   4096
#define GROUPS 32
#define CPG   8
#define NHEADS 4
#define HD    64
#define EPSV  1e-5f
#define QSCALE 0.18033688011112042f   // 0.125 * log2(e)
#define ONE2  0x3C003C00u             // f16x2 {1.0, 1.0}

// ---- scratch (__device__ globals; allocation-free) ----
__device__ __half g_xnb [BATCH*HWN*CH];  // GN(x), [b][n][c]
__device__ __half g_kvnb[BATCH*HWN*CH];  // GN(cond), [b][n][c]
__device__ __half g_qh[BATCH*CH*HWN];    // [b][h][n][d], pre-scaled
__device__ __half g_kh[BATCH*CH*HWN];    // [b][h][n][d]
__device__ __half g_vh[BATCH*CH*HWN];    // [b][c][n]
__device__ __half g_aoh[BATCH*HWN*CH];   // attn out, [b][n][c]
__device__ __half g_wqh[CH*CH], g_wkh[CH*CH], g_wvh[CH*CH], g_woh[CH*CH];

__device__ __forceinline__ uint32_t pack_f16x2(float lo, float hi) {
    uint32_t r;
    asm("cvt.rn.f16x2.f32 %0, %1, %2;" : "=r"(r) : "f"(hi), "f"(lo));
    return r;
}
__device__ __forceinline__ uint32_t ex2_f16x2(uint32_t x) {
    uint32_t r;
    asm("ex2.approx.f16x2 %0, %1;" : "=r"(r) : "r"(x));
    return r;
}
__device__ __forceinline__ void mma_f16(float* d, const uint32_t* a,
                                        uint32_t b0, uint32_t b1) {
    asm volatile(
        "mma.sync.aligned.m16n8k16.row.col.f32.f16.f16.f32 "
        "{%0,%1,%2,%3}, {%4,%5,%6,%7}, {%8,%9}, {%0,%1,%2,%3};\n"
        : "+f"(d[0]), "+f"(d[1]), "+f"(d[2]), "+f"(d[3])
        : "r"(a[0]), "r"(a[1]), "r"(a[2]), "r"(a[3]), "r"(b0), "r"(b1));
}
__device__ __forceinline__ void ldsm_x4(uint32_t& r0, uint32_t& r1,
                                        uint32_t& r2, uint32_t& r3, uint32_t sa) {
    asm volatile("ldmatrix.sync.aligned.m8n8.x4.shared.b16 {%0,%1,%2,%3}, [%4];"
                 : "=r"(r0), "=r"(r1), "=r"(r2), "=r"(r3) : "r"(sa));
}
__device__ __forceinline__ uint32_t smem_u32(const void* p) {
    return (uint32_t)__cvta_generic_to_shared(p);
}

// =====================================================================
// Weight fp32 -> fp16
// =====================================================================
__global__ void wconv_kernel(const float* __restrict__ wq,
                             const float* __restrict__ wk,
                             const float* __restrict__ wv,
                             const float* __restrict__ wo)
{
    const int i = blockIdx.x * 256 + threadIdx.x;
    g_wqh[i] = __float2half_rn(wq[i]);
    g_wkh[i] = __float2half_rn(wk[i]);
    g_wvh[i] = __float2half_rn(wv[i]);
    g_woh[i] = __float2half_rn(wo[i]);
}

// =====================================================================
// GroupNorm -> fp16 [b][n][c]
// =====================================================================
__global__ void gn_kernel(const float* __restrict__ x,
                          const float* __restrict__ cond,
                          const float* __restrict__ gqw, const float* __restrict__ gqb,
                          const float* __restrict__ gkw, const float* __restrict__ gkb)
{
    const int kv = blockIdx.y;
    const float* in  = kv ? cond : x;
    __half* outb = kv ? g_kvnb : g_xnb;
    const float* gw  = kv ? gkw : gqw;
    const float* gb  = kv ? gkb : gqb;

    const int b = blockIdx.x / GROUPS;
    const int g = blockIdx.x % GROUPS;
    const size_t base_off = ((size_t)b*CH + (size_t)g*CPG) * HWN;
    const float4* in4 = (const float4*)(in + base_off);

    float s = 0.f, ss = 0.f;
    for (int i = threadIdx.x; i < (CPG*HWN)/4; i += 256) {
        float4 v = in4[i];
        s  += v.x + v.y + v.z + v.w;
        ss += v.x*v.x + v.y*v.y + v.z*v.z + v.w*v.w;
    }
    #pragma unroll
    for (int off = 16; off; off >>= 1) {
        s  += __shfl_xor_sync(0xffffffffu, s,  off);
        ss += __shfl_xor_sync(0xffffffffu, ss, off);
    }
    __shared__ float sm_s[8], sm_ss[8];
    if ((threadIdx.x & 31) == 0) { sm_s[threadIdx.x>>5] = s; sm_ss[threadIdx.x>>5] = ss; }
    __syncthreads();
    s = 0.f; ss = 0.f;
    #pragma unroll
    for (int w = 0; w < 8; w++) { s += sm_s[w]; ss += sm_ss[w]; }

    const float inv_n = 1.f / (float)(CPG*HWN);
    const float mean  = s * inv_n;
    const float var   = ss * inv_n - mean*mean;
    const float rstd  = rsqrtf(var + EPSV);

    float gwv[CPG], gbv[CPG];
    #pragma unroll
    for (int c = 0; c < CPG; c++) {
        gwv[c] = gw[g*CPG + c] * rstd;
        gbv[c] = gb[g*CPG + c] - mean * gwv[c];
    }

    const float* inp = in + base_off;
    for (int px = threadIdx.x; px < HWN; px += 256) {
        uint32_t p[4];
        #pragma unroll
        for (int c2 = 0; c2 < 4; c2++) {
            float v0 = inp[(size_t)(2*c2  )*HWN + px] * gwv[2*c2  ] + gbv[2*c2  ];
            float v1 = inp[(size_t)(2*c2+1)*HWN + px] * gwv[2*c2+1] + gbv[2*c2+1];
            p[c2] = pack_f16x2(v0, v1);
        }
        *(uint4*)&outb[((size_t)b*HWN + px)*CH + g*CPG] =
            make_uint4(p[0], p[1], p[2], p[3]);
    }
}

// =====================================================================
// fp16 mma GEMM core, double-buffered SMEM (1 sync per k-chunk).
// Block 128ch x 128px; 8 warps 64x32.
// mode: 0=fp32 [b][c][n]+bias+res  1=q f16 [b][h][n][d]*QSCALE
//       2=k f16 [b][h][n][d]       3=v f16 [b][c][n]
// =====================================================================
#define WT_STR 72
#define CS_STR 136
#define GEMM_SMEM 73728

__device__ __forceinline__ void gemm_core(
    char* buf,
    const __half* __restrict__ Wb,
    const __half* __restrict__ Xb,
    const float* __restrict__ bias,
    __half* __restrict__ outb,
    int mode,
    const float* __restrict__ res,
    float* __restrict__ outf,
    int b, int m0, int n0)
{
    __half* Wt[2] = { (__half*)buf, (__half*)buf + 18432 };
    __half* Xt[2] = { (__half*)buf + 9216, (__half*)buf + 27648 };
    __half* Cs = (__half*)buf;   // epilogue restage (q/k)

    const int t = threadIdx.x;
    const int lane = t & 31, warp = t >> 5;
    const int g = lane >> 2, qt = lane & 3;
    const int wm = warp >> 2, wn = warp & 3;
    const int srow = t >> 3, sseg = (t & 7) * 8;

    float acc[4][4][4];
    #pragma unroll
    for (int i = 0; i < 4; i++)
        #pragma unroll
        for (int j = 0; j < 4; j++)
            #pragma unroll
            for (int l = 0; l < 4; l++) acc[i][j][l] = 0.f;

    uint4 wreg[4], xreg[4];
    #pragma unroll
    for (int it = 0; it < 4; it++) {
        int row = srow + it*32;
        wreg[it] = *(const uint4*)&Wb[(size_t)(m0+row)*CH + sseg];
        xreg[it] = *(const uint4*)&Xb[((size_t)b*HWN + n0+row)*CH + sseg];
    }
    #pragma unroll
    for (int it = 0; it < 4; it++) {
        int row = srow + it*32;
        *(uint4*)&Wt[0][row*WT_STR + sseg] = wreg[it];
        *(uint4*)&Xt[0][row*WT_STR + sseg] = xreg[it];
    }
    __syncthreads();

    for (int c = 0; c < 4; c++) {
        const int cur = c & 1;
        if (c + 1 < 4) {
            const int k0 = (c+1)*64;
            #pragma unroll
            for (int it = 0; it < 4; it++) {
                int row = srow + it*32;
                wreg[it] = *(const uint4*)&Wb[(size_t)(m0+row)*CH + k0 + sseg];
                xreg[it] = *(const uint4*)&Xb[((size_t)b*HWN + n0+row)*CH + k0 + sseg];
            }
        }
        const __half* Wc = Wt[cur];
        const __half* Xc = Xt[cur];
        #pragma unroll
        for (int kc = 0; kc < 4; kc++) {
            uint32_t a[4][4], b0[4], b1[4];
            #pragma unroll
            for (int mf = 0; mf < 4; mf++) {
                const __half* wr = Wc + (wm*64 + mf*16 + g)*WT_STR + kc*16 + 2*qt;
                a[mf][0] = *(const uint32_t*)wr;
                a[mf][1] = *(const uint32_t*)(wr + 8*WT_STR);
                a[mf][2] = *(const uint32_t*)(wr + 8);
                a[mf][3] = *(const uint32_t*)(wr + 8*WT_STR + 8);
            }
            #pragma unroll
            for (int nf = 0; nf < 4; nf++) {
                const __half* xr = Xc + (wn*32 + nf*8 + g)*WT_STR + kc*16 + 2*qt;
                b0[nf] = *(const uint32_t*)xr;
                b1[nf] = *(const uint32_t*)(xr + 8);
            }
            #pragma unroll
            for (int mf = 0; mf < 4; mf++)
                #pragma unroll
                for (int nf = 0; nf < 4; nf++)
                    mma_f16(acc[mf][nf], a[mf], b0[nf], b1[nf]);
        }
        if (c + 1 < 4) {
            #pragma unroll
            for (int it = 0; it < 4; it++) {
                int row = srow + it*32;
                *(uint4*)&Wt[1-cur][row*WT_STR + sseg] = wreg[it];
                *(uint4*)&Xt[1-cur][row*WT_STR + sseg] = xreg[it];
            }
            __syncthreads();
        }
    }

    if (mode == 0) {
        #pragma unroll
        for (int mf = 0; mf < 4; mf++) {
            const int ch = m0 + wm*64 + mf*16 + g;
            const float bb0 = bias[ch], bb1 = bias[ch + 8];
            #pragma unroll
            for (int nf = 0; nf < 4; nf++) {
                const int px = n0 + wn*32 + nf*8 + 2*qt;
                const size_t o0 = ((size_t)b*CH + ch)*HWN + px;
                const size_t o1 = ((size_t)b*CH + ch + 8)*HWN + px;
                float2 r0 = *(const float2*)&res[o0];
                float2 r1 = *(const float2*)&res[o1];
                *(float2*)&outf[o0] = make_float2(acc[mf][nf][0] + bb0 + r0.x,
                                                  acc[mf][nf][1] + bb0 + r0.y);
                *(float2*)&outf[o1] = make_float2(acc[mf][nf][2] + bb1 + r1.x,
                                                  acc[mf][nf][3] + bb1 + r1.y);
            }
        }
    } else if (mode == 3) {
        #pragma unroll
        for (int mf = 0; mf < 4; mf++) {
            const int ch = m0 + wm*64 + mf*16 + g;
            const float bb0 = bias[ch], bb1 = bias[ch + 8];
            #pragma unroll
            for (int nf = 0; nf < 4; nf++) {
                const int px = n0 + wn*32 + nf*8 + 2*qt;
                *(uint32_t*)&outb[((size_t)b*CH + ch)*HWN + px] =
                    pack_f16x2(acc[mf][nf][0] + bb0, acc[mf][nf][1] + bb0);
                *(uint32_t*)&outb[((size_t)b*CH + ch + 8)*HWN + px] =
                    pack_f16x2(acc[mf][nf][2] + bb1, acc[mf][nf][3] + bb1);
            }
        }
    } else {
        const float sc = (mode == 1) ? QSCALE : 1.0f;
        __syncthreads();
        #pragma unroll
        for (int mf = 0; mf < 4; mf++) {
            const int chl = wm*64 + mf*16 + g;
            const float bb0 = bias[m0 + chl], bb1 = bias[m0 + chl + 8];
            #pragma unroll
            for (int nf = 0; nf < 4; nf++) {
                const int pxl = wn*32 + nf*8 + 2*qt;
                Cs[pxl*CS_STR + chl]       = __float2half_rn((acc[mf][nf][0] + bb0) * sc);
                Cs[(pxl+1)*CS_STR + chl]   = __float2half_rn((acc[mf][nf][1] + bb0) * sc);
                Cs[pxl*CS_STR + chl+8]     = __float2half_rn((acc[mf][nf][2] + bb1) * sc);
                Cs[(pxl+1)*CS_STR + chl+8] = __float2half_rn((acc[mf][nf][3] + bb1) * sc);
            }
        }
        __syncthreads();
        #pragma unroll
        for (int it = 0; it < 8; it++) {
            int i = t + it*256;
            int px = i >> 4, seg = i & 15;
            uint4 v = *(const uint4*)&Cs[px*CS_STR + seg*8];
            const int h = (m0 >> 6) + (seg >> 3);
            const int d = (seg & 7) * 8;
            *(uint4*)&outb[((size_t)(b*NHEADS + h)*HWN + n0 + px)*HD + d] = v;
        }
    }
}

// fused q/k/v launch: grid (32, 2, 12); z = mat*4 + b
__global__ void __launch_bounds__(256, 2) gemm_qkv_kernel(
    const float* __restrict__ bq, const float* __restrict__ bk,
    const float* __restrict__ bv)
{
    extern __shared__ char dbuf[];
    const int z = blockIdx.z;
    const int mat = z >> 2, b = z & 3;
    const __half* W    = (mat == 0) ? g_wqh : (mat == 1) ? g_wkh : g_wvh;
    const float* bias  = (mat == 0) ? bq   : (mat == 1) ? bk   : bv;
    __half* out        = (mat == 0) ? g_qh : (mat == 1) ? g_kh : g_vh;
    const __half* X    = (mat == 0) ? g_xnb : g_kvnb;
    gemm_core(dbuf, W, X, bias, out, mat + 1, nullptr, nullptr,
              b, blockIdx.y * 128, blockIdx.x * 128);
}

// wo projection: grid (32, 2, 4)
__global__ void __launch_bounds__(256, 2) gemm_wo_kernel(
    const float* __restrict__ bo, const float* __restrict__ res,
    float* __restrict__ outf)
{
    extern __shared__ char dbuf[];
    gemm_core(dbuf, g_woh, g_aoh, bo, nullptr, 0, res, outf,
              blockIdx.z, blockIdx.y * 128, blockIdx.x * 128);
}

// =====================================================================
// fp16 mma flash attention. R7 staging (reg prefetch before compute).
// Softmax: cvt.f16x2 + ex2.approx.f16x2; row sums via mma with ones.
// =====================================================================
#define KS_STR 72

__global__ void __launch_bounds__(256, 2) attn_mma_f16()
{
    __shared__ __half Ks[64*KS_STR];   // [key][d]
    __shared__ __half Vs[64*KS_STR];   // [d][key]

    const int bh = blockIdx.y;
    const int b = bh >> 2, h = bh & 3;
    const int n0 = blockIdx.x * 128;
    const __half* Qg = g_qh + (size_t)(b*NHEADS + h) * HWN * HD;
    const __half* Kg = g_kh + (size_t)(b*NHEADS + h) * HWN * HD;
    const __half* Vg = g_vh + ((size_t)b*CH + (size_t)h*HD) * HWN;

    const int t = threadIdx.x;
    const int lane = t & 31, warp = t >> 5;
    const int g = lane >> 2, tid = lane & 3;
    const int nb = warp * 16;

    const uint32_t lds_off = (uint32_t)(((lane & 7) * KS_STR + (lane >> 3) * 8) * 2);
    const uint32_t ks_base = smem_u32(Ks) + lds_off;
    const uint32_t vs_base = smem_u32(Vs) + lds_off;

    const int srow0 = t >> 3, sseg = (t & 7) * 8;
    const int srow1 = srow0 + 32;

    // Q A-fragments (persist)
    uint32_t qa[4][4];
    {
        const __half* q0 = Qg + (size_t)(n0 + nb + g) * HD;
        const __half* q1 = Qg + (size_t)(n0 + nb + g + 8) * HD;
        #pragma unroll
        for (int kc = 0; kc < 4; kc++) {
            qa[kc][0] = *(const uint32_t*)(q0 + kc*16 + 2*tid);
            qa[kc][1] = *(const uint32_t*)(q1 + kc*16 + 2*tid);
            qa[kc][2] = *(const uint32_t*)(q0 + kc*16 + 2*tid + 8);
            qa[kc][3] = *(const uint32_t*)(q1 + kc*16 + 2*tid + 8);
        }
    }

    float oa[8][4];
    #pragma unroll
    for (int i = 0; i < 8; i++)
        #pragma unroll
        for (int j = 0; j < 4; j++) oa[i][j] = 0.f;
    float rs[4] = {0.f, 0.f, 0.f, 0.f};   // row-sum accumulator (mma C-frag)

    // prefetch tile 0
    uint4 kreg0 = *(const uint4*)(Kg + (size_t)srow0*HD + sseg);
    uint4 kreg1 = *(const uint4*)(Kg + (size_t)srow1*HD + sseg);
    uint4 vreg0 = *(const uint4*)(Vg + (size_t)srow0*HWN + sseg);
    uint4 vreg1 = *(const uint4*)(Vg + (size_t)srow1*HWN + sseg);

    for (int j0 = 0; j0 < HWN; j0 += 64) {
        __syncthreads();
        *(uint4*)(Ks + srow0*KS_STR + sseg) = kreg0;
        *(uint4*)(Ks + srow1*KS_STR + sseg) = kreg1;
        *(uint4*)(Vs + srow0*KS_STR + sseg) = vreg0;
        *(uint4*)(Vs + srow1*KS_STR + sseg) = vreg1;
        __syncthreads();

        if (j0 + 64 < HWN) {
            const int j1 = j0 + 64;
            kreg0 = *(const uint4*)(Kg + (size_t)(j1+srow0)*HD + sseg);
            kreg1 = *(const uint4*)(Kg + (size_t)(j1+srow1)*HD + sseg);
            vreg0 = *(const uint4*)(Vg + (size_t)srow0*HWN + j1 + sseg);
            vreg1 = *(const uint4*)(Vg + (size_t)srow1*HWN + j1 + sseg);
        }

        // ---- S = Q K^T ----
        float sa[8][4];
        #pragma unroll
        for (int mt = 0; mt < 8; mt++) {
            uint32_t kb[8];
            const uint32_t base = ks_base + (uint32_t)(mt * 8 * KS_STR * 2);
            ldsm_x4(kb[0], kb[1], kb[2], kb[3], base);
            ldsm_x4(kb[4], kb[5], kb[6], kb[7], base + 64);
            #pragma unroll
            for (int j = 0; j < 4; j++) sa[mt][j] = 0.f;
            #pragma unroll
            for (int kc = 0; kc < 4; kc++)
                mma_f16(sa[mt], qa[kc], kb[2*kc], kb[2*kc+1]);
        }

        // ---- softmax: f16x2 exp2; row sums via mma with ones ----
        uint32_t pe[4][4];
        #pragma unroll
        for (int kc = 0; kc < 4; kc++) {
            pe[kc][0] = ex2_f16x2(pack_f16x2(sa[2*kc][0],   sa[2*kc][1]));
            pe[kc][1] = ex2_f16x2(pack_f16x2(sa[2*kc][2],   sa[2*kc][3]));
            pe[kc][2] = ex2_f16x2(pack_f16x2(sa[2*kc+1][0], sa[2*kc+1][1]));
            pe[kc][3] = ex2_f16x2(pack_f16x2(sa[2*kc+1][2], sa[2*kc+1][3]));
            mma_f16(rs, pe[kc], ONE2, ONE2);
        }

        // ---- O += P V^T ----
        #pragma unroll
        for (int dt = 0; dt < 8; dt++) {
            uint32_t vb[8];
            const uint32_t base = vs_base + (uint32_t)(dt * 8 * KS_STR * 2);
            ldsm_x4(vb[0], vb[1], vb[2], vb[3], base);
            ldsm_x4(vb[4], vb[5], vb[6], vb[7], base + 64);
            #pragma unroll
            for (int kc = 0; kc < 4; kc++)
                mma_f16(oa[dt], pe[kc], vb[2*kc], vb[2*kc+1]);
        }
    }

    // ---- normalize + store f16 [b][n][c] (rs is quad-uniform) ----
    const float li0 = 1.f / rs[0];
    const float li1 = 1.f / rs[2];

    __half* O0 = g_aoh + ((size_t)b*HWN + n0 + nb + g)*CH + h*HD + 2*tid;
    __half* O1 = O0 + 8*CH;
    #pragma unroll
    for (int dt = 0; dt < 8; dt++) {
        *(uint32_t*)(O0 + dt*8) = pack_f16x2(oa[dt][0]*li0, oa[dt][1]*li0);
        *(uint32_t*)(O1 + dt*8) = pack_f16x2(oa[dt][2]*li1, oa[dt][3]*li1);
    }
}

// =====================================================================
extern "C" void kernel_launch(void* const* d_in, const int* in_sizes, int n_in,
                              void* d_out, int out_size)
{
    const float* x    = (const float*)d_in[0];
    const float* cond = (const float*)d_in[1];
    const float* gqw  = (const float*)d_in[2];
    const float* gqb  = (const float*)d_in[3];
    const float* gkw  = (const float*)d_in[4];
    const float* gkb  = (const float*)d_in[5];
    const float* wq   = (const float*)d_in[6];
    const float* bq   = (const float*)d_in[7];
    const float* wk   = (const float*)d_in[8];
    const float* bk   = (const float*)d_in[9];
    const float* wv   = (const float*)d_in[10];
    const float* bv   = (const float*)d_in[11];
    const float* wo   = (const float*)d_in[12];
    const float* bo   = (const float*)d_in[13];
    float* out = (float*)d_out;

    cudaFuncSetAttribute(gemm_qkv_kernel,
                         cudaFuncAttributeMaxDynamicSharedMemorySize, GEMM_SMEM);
    cudaFuncSetAttribute(gemm_wo_kernel,
                         cudaFuncAttributeMaxDynamicSharedMemorySize, GEMM_SMEM);

    wconv_kernel<<<CH*CH/256, 256>>>(wq, wk, wv, wo);
    gn_kernel<<<dim3(BATCH*GROUPS, 2), 256>>>(x, cond, gqw, gqb, gkw, gkb);

    gemm_qkv_kernel<<<dim3(HWN/128, CH/128, 12), 256, GEMM_SMEM>>>(bq, bk, bv);

    attn_mma_f16<<<dim3(HWN/128, BATCH*NHEADS), 256>>>();

    gemm_wo_kernel<<<dim3(HWN/128, CH/128, BATCH), 256, GEMM_SMEM>>>(bo, x, out);
}